// round 2
// baseline (speedup 1.0000x reference)
#include <cuda_runtime.h>
#include <math.h>

// ---------------------------------------------------------------------------
// Mesh rasterizer — z-sorted faces with per-pixel early termination.
// Output layout (float32): [pix_feats npix*C][p2f npix][zbuf npix][bary 3npix][dists npix]
// ---------------------------------------------------------------------------

#define VMAX    16384
#define FMAX    32768
#define PIXMAX  65536
#define NBUCK   1024
#define CH      128
#define NCHMAX  (FMAX / CH)      // 256
#define TILE    8

__device__ float g_vx[VMAX], g_vy[VMAX], g_vz[VMAX];

// unsorted per-face data (indexed by original face id; used by scatter + merge)
__device__ float g_fx0[FMAX], g_fy0[FMAX], g_fz0[FMAX];
__device__ float g_fx1[FMAX], g_fy1[FMAX], g_fz1[FMAX];
__device__ float g_fx2[FMAX], g_fy2[FMAX], g_fz2[FMAX];
__device__ float g_finva[FMAX], g_fz01[FMAX], g_fzs[FMAX];
__device__ float g_bxmin[FMAX], g_bxmax[FMAX], g_bymin[FMAX], g_bymax[FMAX];

// sorted (bucketed by zskip) compacted valid faces
__device__ float o_x0[FMAX], o_y0[FMAX], o_z0[FMAX];
__device__ float o_x1[FMAX], o_y1[FMAX], o_z1[FMAX];
__device__ float o_x2[FMAX], o_y2[FMAX], o_z2[FMAX];
__device__ float o_inva[FMAX], o_z01[FMAX], o_zs[FMAX];
__device__ float o_bxmin[FMAX], o_bxmax[FMAX], o_bymin[FMAX], o_bymax[FMAX];
__device__ int   o_fid[FMAX];

__device__ unsigned g_zmin_u, g_zmax_u;
__device__ int      g_hist[NBUCK];
__device__ int      g_boff[NBUCK];
__device__ int      g_nvalid;
__device__ unsigned g_chmin_u[NCHMAX];
__device__ float    g_chsuf[NCHMAX];

__device__ float g_pz[PIXMAX];
__device__ int   g_pidx[PIXMAX];
__device__ float g_wb[PIXMAX * 3];

__device__ __forceinline__ float f_inf() { return __int_as_float(0x7f800000); }

// order-preserving float<->uint maps (valid for all signs)
__device__ __forceinline__ unsigned f2o(float f) {
    unsigned u = __float_as_uint(f);
    return (u & 0x80000000u) ? ~u : (u | 0x80000000u);
}
__device__ __forceinline__ float o2f(unsigned u) {
    unsigned v = (u & 0x80000000u) ? (u & 0x7fffffffu) : ~u;
    return __uint_as_float(v);
}

// ------------------------- init (reset per launch) -------------------------
__global__ void k_init()
{
    int t = threadIdx.x;
    if (t < NBUCK)  g_hist[t] = 0;
    if (t < NCHMAX) g_chmin_u[t] = 0xFFFFFFFFu;
    if (t == 0) { g_zmin_u = 0xFFFFFFFFu; g_zmax_u = 0u; g_nvalid = 0; }
}

// ------------------------- vertex transform -------------------------------
__global__ void k_vertex(const float* __restrict__ pos,
                         const float* __restrict__ K,
                         const float* __restrict__ RT,
                         int V, float Wf, float Hf)
{
    int v = blockIdx.x * blockDim.x + threadIdx.x;
    if (v >= V) return;
    float x = pos[3 * v + 0], y = pos[3 * v + 1], z = pos[3 * v + 2];

    float vv[3];
#pragma unroll
    for (int j = 0; j < 3; j++) {
        float sg = (j == 2) ? 1.0f : -1.0f;
        float Rp0 = __fmul_rn(RT[j * 4 + 0], sg);
        float Rp1 = __fmul_rn(RT[j * 4 + 1], sg);
        float Rp2 = __fmul_rn(RT[j * 4 + 2], sg);
        float Tp  = __fmul_rn(RT[j * 4 + 3], sg);
        float a = __fmul_rn(x, Rp0);
        a = __fadd_rn(a, __fmul_rn(y, Rp1));
        a = __fadd_rn(a, __fmul_rn(z, Rp2));
        vv[j] = __fadd_rn(a, Tp);
    }
    float scale = __fmul_rn(fminf(Hf, Wf), 0.5f);
    float fx = __fdiv_rn(K[0], scale);
    float fy = __fdiv_rn(K[4], scale);
    float p0x = -__fdiv_rn(__fsub_rn(K[2], __fmul_rn(Wf, 0.5f)), scale);
    float p0y = -__fdiv_rn(__fsub_rn(K[5], __fmul_rn(Hf, 0.5f)), scale);

    float zz = vv[2];
    g_vx[v] = __fadd_rn(__fdiv_rn(__fmul_rn(fx, vv[0]), zz), p0x);
    g_vy[v] = __fadd_rn(__fdiv_rn(__fmul_rn(fy, vv[1]), zz), p0y);
    g_vz[v] = zz;
}

// ------------------------- per-face precompute -----------------------------
__global__ void k_face(const int* __restrict__ faces, int Fn)
{
    int f = blockIdx.x * blockDim.x + threadIdx.x;
    if (f >= Fn) return;
    int i0 = faces[3 * f + 0], i1 = faces[3 * f + 1], i2 = faces[3 * f + 2];
    float x0 = g_vx[i0], y0 = g_vy[i0], z0 = g_vz[i0];
    float x1 = g_vx[i1], y1 = g_vy[i1], z1 = g_vz[i1];
    float x2 = g_vx[i2], y2 = g_vy[i2], z2 = g_vz[i2];

    float area = __fsub_rn(__fmul_rn(__fsub_rn(x1, x0), __fsub_rn(y2, y0)),
                           __fmul_rn(__fsub_rn(y1, y0), __fsub_rn(x2, x0)));
    bool ok = (area > 1e-8f) && (z0 > 0.0f) && (z1 > 0.0f) && (z2 > 0.0f);
    float inva = ok ? __fdiv_rn(1.0f, area) : 0.0f;

    g_fx0[f] = x0; g_fy0[f] = y0; g_fz0[f] = z0;
    g_fx1[f] = x1; g_fy1[f] = y1; g_fz1[f] = z1;
    g_fx2[f] = x2; g_fy2[f] = y2; g_fz2[f] = z2;
    g_finva[f] = inva;
    g_fz01[f]  = __fmul_rn(z0, z1);
    float zmn = fminf(z0, fminf(z1, z2));
    float zskip = zmn - 1e-4f;
    g_fzs[f] = zskip;
    const float M = 5e-3f;
    g_bxmin[f] = fminf(x0, fminf(x1, x2)) - M;
    g_bxmax[f] = fmaxf(x0, fmaxf(x1, x2)) + M;
    g_bymin[f] = fminf(y0, fminf(y1, y2)) - M;
    g_bymax[f] = fmaxf(y0, fmaxf(y1, y2)) + M;

    if (ok) {
        atomicMin(&g_zmin_u, f2o(zskip));
        atomicMax(&g_zmax_u, f2o(zskip));
    }
}

__device__ __forceinline__ int bucket_of(float z)
{
    float zmin = o2f(g_zmin_u), zmax = o2f(g_zmax_u);
    float r = zmax - zmin;
    int b = 0;
    if (r > 0.0f) b = (int)(((z - zmin) / r) * (float)NBUCK);
    if (b < 0) b = 0;
    if (b > NBUCK - 1) b = NBUCK - 1;
    return b;
}

__global__ void k_hist(int Fn)
{
    int f = blockIdx.x * blockDim.x + threadIdx.x;
    if (f >= Fn) return;
    if (g_finva[f] > 0.0f) atomicAdd(&g_hist[bucket_of(g_fzs[f])], 1);
}

__global__ void k_scan()   // 1 block, NBUCK threads
{
    __shared__ int tmp[NBUCK];
    int t = threadIdx.x;
    int v = g_hist[t];
    tmp[t] = v;
    __syncthreads();
    for (int off = 1; off < NBUCK; off <<= 1) {
        int a = 0;
        if (t >= off) a = tmp[t - off];
        __syncthreads();
        if (t >= off) tmp[t] += a;
        __syncthreads();
    }
    g_boff[t] = tmp[t] - v;
    if (t == NBUCK - 1) g_nvalid = tmp[t];
}

__global__ void k_scatter(int Fn)
{
    int f = blockIdx.x * blockDim.x + threadIdx.x;
    if (f >= Fn) return;
    if (g_finva[f] <= 0.0f) return;
    float zs = g_fzs[f];
    int b = bucket_of(zs);
    int p = atomicAdd(&g_boff[b], 1);
    o_x0[p] = g_fx0[f]; o_y0[p] = g_fy0[f]; o_z0[p] = g_fz0[f];
    o_x1[p] = g_fx1[f]; o_y1[p] = g_fy1[f]; o_z1[p] = g_fz1[f];
    o_x2[p] = g_fx2[f]; o_y2[p] = g_fy2[f]; o_z2[p] = g_fz2[f];
    o_inva[p] = g_finva[f]; o_z01[p] = g_fz01[f]; o_zs[p] = zs;
    o_bxmin[p] = g_bxmin[f]; o_bxmax[p] = g_bxmax[f];
    o_bymin[p] = g_bymin[f]; o_bymax[p] = g_bymax[f];
    o_fid[p] = f;
    atomicMin(&g_chmin_u[p / CH], f2o(zs));
}

__global__ void k_suffix()   // 1 thread: suffix-min of chunk minima
{
    int n = g_nvalid;
    int nch = (n + CH - 1) / CH;
    float suf = f_inf();
    for (int c = nch - 1; c >= 0; c--) {
        float m = o2f(g_chmin_u[c]);
        suf = fminf(suf, m);
        g_chsuf[c] = suf;
    }
}

// exact perspective-correct bary + zpix, replicating reference op order
__device__ __forceinline__ void eval_exact(
    float px, float py,
    float x0, float y0, float z0, float x1, float y1, float z1,
    float x2, float y2, float z2, float inva, float z01,
    bool& inside, float& zpix, float& d0, float& d1, float& d2)
{
    float dx0 = __fsub_rn(x0, px), dy0 = __fsub_rn(y0, py);
    float dx1 = __fsub_rn(x1, px), dy1 = __fsub_rn(y1, py);
    float dx2 = __fsub_rn(x2, px), dy2 = __fsub_rn(y2, py);
    float w0 = __fmul_rn(__fsub_rn(__fmul_rn(dx1, dy2), __fmul_rn(dy1, dx2)), inva);
    float w1 = __fmul_rn(__fsub_rn(__fmul_rn(dx2, dy0), __fmul_rn(dy2, dx0)), inva);
    float w2 = __fmul_rn(__fsub_rn(__fmul_rn(dx0, dy1), __fmul_rn(dy0, dx1)), inva);
    inside = (w0 >= 0.0f) && (w1 >= 0.0f) && (w2 >= 0.0f);
    if (!inside) { zpix = f_inf(); d0 = d1 = d2 = 0.0f; return; }
    float l0 = __fmul_rn(__fmul_rn(w0, z1), z2);
    float l1 = __fmul_rn(__fmul_rn(z0, w1), z2);
    float l2 = __fmul_rn(z01, w2);
    float s  = __fadd_rn(__fadd_rn(l0, l1), l2);
    float sden = (s == 0.0f) ? 1.0f : s;
    float b0 = __fdiv_rn(l0, sden);
    float b1 = __fdiv_rn(l1, sden);
    float b2 = __fdiv_rn(l2, sden);
    b0 = fmaxf(b0, 0.0f); b1 = fmaxf(b1, 0.0f); b2 = fmaxf(b2, 0.0f);
    float sb = __fadd_rn(__fadd_rn(b0, b1), b2);
    float den2 = fmaxf(sb, 1e-8f);
    d0 = __fdiv_rn(b0, den2);
    d1 = __fdiv_rn(b1, den2);
    d2 = __fdiv_rn(b2, den2);
    zpix = __fadd_rn(__fadd_rn(__fmul_rn(d0, z0), __fmul_rn(d1, z1)),
                     __fmul_rn(d2, z2));
}

// ------------------------- rasterize (sorted, early exit) ------------------
__global__ void __launch_bounds__(64) k_raster(int W, int H)
{
    __shared__ float s[16][CH];
    __shared__ int   sidx[CH];
    int tilesX = (W + TILE - 1) / TILE;
    int tx = blockIdx.x % tilesX, ty = blockIdx.x / tilesX;
    int lx = threadIdx.x & (TILE - 1), ly = threadIdx.x >> 3;
    int j = tx * TILE + lx, i = ty * TILE + ly;
    bool live = (j < W) && (i < H);

    float px = 0.0f, py = 0.0f;
    if (live) {
        px = __fsub_rn(1.0f, __fdiv_rn(__fadd_rn(__fmul_rn(2.0f, (float)j), 1.0f), (float)W));
        py = __fsub_rn(1.0f, __fdiv_rn(__fadd_rn(__fmul_rn(2.0f, (float)i), 1.0f), (float)H));
    }

    int n = g_nvalid;
    int nch = (n + CH - 1) / CH;
    float bestZ = f_inf();
    int   bestI = -1;
    bool  done  = !live;

    for (int c = 0; c < nch; c++) {
        // all remaining faces have zskip >= g_chsuf[c]: safe permanent exit
        done = done || (g_chsuf[c] >= bestZ);
        if (__syncthreads_and((int)done)) break;

        int base = c * CH;
        int cnt = min(CH, n - base);
        for (int t = threadIdx.x; t < cnt; t += 64) {
            int g = base + t;
            s[0][t]  = o_x0[g];   s[1][t]  = o_y0[g];   s[2][t]  = o_z0[g];
            s[3][t]  = o_x1[g];   s[4][t]  = o_y1[g];   s[5][t]  = o_z1[g];
            s[6][t]  = o_x2[g];   s[7][t]  = o_y2[g];   s[8][t]  = o_z2[g];
            s[9][t]  = o_inva[g]; s[10][t] = o_z01[g];  s[11][t] = o_zs[g];
            s[12][t] = o_bxmin[g]; s[13][t] = o_bxmax[g];
            s[14][t] = o_bymin[g]; s[15][t] = o_bymax[g];
            sidx[t]  = o_fid[g];
        }
        __syncthreads();
        if (done) continue;
        for (int k = 0; k < cnt; k++) {
            if (s[11][k] >= bestZ) continue;                  // conservative z cull
            if (px < s[12][k] || px > s[13][k] ||
                py < s[14][k] || py > s[15][k]) continue;     // conservative bbox
            bool inside; float zpix, d0, d1, d2;
            eval_exact(px, py,
                       s[0][k], s[1][k], s[2][k],
                       s[3][k], s[4][k], s[5][k],
                       s[6][k], s[7][k], s[8][k],
                       s[9][k], s[10][k],
                       inside, zpix, d0, d1, d2);
            if (inside) {
                int idx = sidx[k];
                // lexicographic (z, origIdx): exactly argmin-first semantics
                if (zpix < bestZ || (zpix == bestZ && idx < bestI)) {
                    bestZ = zpix; bestI = idx;
                }
            }
        }
    }
    if (live) {
        int pix = i * W + j;
        g_pz[pix]   = bestZ;
        g_pidx[pix] = bestI;
    }
}

// ------------------------- merge + scalar outputs --------------------------
__global__ void k_merge(float* __restrict__ out, int W, int H, int npix, int C)
{
    int pix = blockIdx.x * blockDim.x + threadIdx.x;
    if (pix >= npix) return;
    int bi = g_pidx[pix];
    float bz = g_pz[pix];

    float p2f, zb, ba0, ba1, ba2, ds;
    if (bi < 0) {
        p2f = -1.0f; zb = -1.0f; ba0 = ba1 = ba2 = -1.0f; ds = -1.0f;
    } else {
        int i = pix / W, j = pix % W;
        float px = __fsub_rn(1.0f, __fdiv_rn(__fadd_rn(__fmul_rn(2.0f, (float)j), 1.0f), (float)W));
        float py = __fsub_rn(1.0f, __fdiv_rn(__fadd_rn(__fmul_rn(2.0f, (float)i), 1.0f), (float)H));
        bool inside; float zpix, d0, d1, d2;
        eval_exact(px, py,
                   g_fx0[bi], g_fy0[bi], g_fz0[bi],
                   g_fx1[bi], g_fy1[bi], g_fz1[bi],
                   g_fx2[bi], g_fy2[bi], g_fz2[bi],
                   g_finva[bi], g_fz01[bi],
                   inside, zpix, d0, d1, d2);
        p2f = (float)bi; zb = bz; ba0 = d0; ba1 = d1; ba2 = d2; ds = 0.0f;
        g_wb[3 * pix + 0] = d0; g_wb[3 * pix + 1] = d1; g_wb[3 * pix + 2] = d2;
    }

    size_t o1 = (size_t)npix * (size_t)C;
    out[o1 + pix] = p2f;
    out[o1 + npix + pix] = zb;
    out[o1 + 2 * (size_t)npix + 3 * (size_t)pix + 0] = ba0;
    out[o1 + 2 * (size_t)npix + 3 * (size_t)pix + 1] = ba1;
    out[o1 + 2 * (size_t)npix + 3 * (size_t)pix + 2] = ba2;
    out[o1 + 5 * (size_t)npix + pix] = ds;
}

// ------------------------- feature interpolation ---------------------------
__global__ void k_feats(float* __restrict__ out,
                        const float* __restrict__ feats,
                        const int* __restrict__ faces,
                        int npix, int C)
{
    int gw = (blockIdx.x * blockDim.x + threadIdx.x) >> 5;
    int lane = threadIdx.x & 31;
    if (gw >= npix) return;
    float* o = out + (size_t)gw * (size_t)C;
    int bi = g_pidx[gw];
    if (bi < 0) {
        for (int c = lane; c < C; c += 32) o[c] = 0.0f;
        return;
    }
    int v0 = faces[3 * bi + 0], v1 = faces[3 * bi + 1], v2 = faces[3 * bi + 2];
    float b0 = g_wb[3 * gw + 0], b1 = g_wb[3 * gw + 1], b2 = g_wb[3 * gw + 2];
    const float* f0 = feats + (size_t)v0 * (size_t)C;
    const float* f1 = feats + (size_t)v1 * (size_t)C;
    const float* f2 = feats + (size_t)v2 * (size_t)C;
    for (int c = lane; c < C; c += 32) {
        float val = __fadd_rn(__fadd_rn(__fmul_rn(b0, f0[c]),
                                        __fmul_rn(b1, f1[c])),
                              __fmul_rn(b2, f2[c]));
        o[c] = val;
    }
}

// ------------------------- launch -----------------------------------------
extern "C" void kernel_launch(void* const* d_in, const int* in_sizes, int n_in,
                              void* d_out, int out_size)
{
    const float* positions = (const float*)d_in[0];
    const float* features  = (const float*)d_in[1];
    const int*   faces     = (const int*)d_in[2];
    const float* K         = (const float*)d_in[3];
    const float* RT        = (const float*)d_in[4];

    int V  = in_sizes[0] / 3;
    int C  = in_sizes[1] / V;
    int Fn = in_sizes[2] / 3;
    int npix = out_size / (C + 6);
    int W = (int)(sqrt((double)npix) + 0.5);
    if (W <= 0) W = 1;
    int H = npix / W;
    float* out = (float*)d_out;

    k_init<<<1, 1024>>>();
    k_vertex<<<(V + 255) / 256, 256>>>(positions, K, RT, V, (float)W, (float)H);
    k_face<<<(Fn + 255) / 256, 256>>>(faces, Fn);
    k_hist<<<(Fn + 255) / 256, 256>>>(Fn);
    k_scan<<<1, NBUCK>>>();
    k_scatter<<<(Fn + 255) / 256, 256>>>(Fn);
    k_suffix<<<1, 1>>>();

    int tilesX = (W + TILE - 1) / TILE;
    int tilesY = (H + TILE - 1) / TILE;
    k_raster<<<tilesX * tilesY, 64>>>(W, H);

    k_merge<<<(npix + 255) / 256, 256>>>(out, W, H, npix, C);
    k_feats<<<(npix + 7) / 8, 256>>>(out, features, faces, npix, C);
}

// round 3
// speedup vs baseline: 2.8781x; 2.8781x over previous
#include <cuda_runtime.h>
#include <math.h>

// ---------------------------------------------------------------------------
// Mesh rasterizer — screen-space tile binning + per-pixel z-cull.
// Output (float32): [pix_feats npix*C][p2f npix][zbuf npix][bary 3npix][dists npix]
// ---------------------------------------------------------------------------

#define VMAX    16384
#define FMAX    32768
#define PIXMAX  65536
#define TILE    16
#define MAXT    4096          // max tiles
#define TLCAP   (4*1024*1024) // tile-list capacity (entries)
#define NSPLIT  4
#define CHK     256

__device__ float g_vx[VMAX], g_vy[VMAX], g_vz[VMAX];

// per-face packed records (indexed by original face id)
// pa=(x0,y0,z0,inva) pb=(x1,y1,z1,z0*z1) pc=(x2,y2,z2,zskip) pd=(bxmin,bxmax,bymin,bymax)
__device__ float4 g_pa[FMAX], g_pb[FMAX], g_pc[FMAX], g_pd[FMAX];

// tile binning
__device__ int g_tcount[MAXT];
__device__ int g_tstart[MAXT];
__device__ int g_tcur[MAXT];
__device__ int g_tlist[TLCAP];

// per-pixel per-split candidates
__device__ float g_pz[NSPLIT * PIXMAX];
__device__ int   g_pidx[NSPLIT * PIXMAX];
__device__ float g_wb[PIXMAX * 3];
__device__ int   g_widx[PIXMAX];

__device__ __forceinline__ float f_inf() { return __int_as_float(0x7f800000); }

// ------------------------- vertex transform -------------------------------
__global__ void k_vertex(const float* __restrict__ pos,
                         const float* __restrict__ K,
                         const float* __restrict__ RT,
                         int V, float Wf, float Hf)
{
    int v = blockIdx.x * blockDim.x + threadIdx.x;
    if (v >= V) return;
    float x = pos[3 * v + 0], y = pos[3 * v + 1], z = pos[3 * v + 2];

    float vv[3];
#pragma unroll
    for (int j = 0; j < 3; j++) {
        float sg = (j == 2) ? 1.0f : -1.0f;
        float Rp0 = __fmul_rn(RT[j * 4 + 0], sg);
        float Rp1 = __fmul_rn(RT[j * 4 + 1], sg);
        float Rp2 = __fmul_rn(RT[j * 4 + 2], sg);
        float Tp  = __fmul_rn(RT[j * 4 + 3], sg);
        float a = __fmul_rn(x, Rp0);
        a = __fadd_rn(a, __fmul_rn(y, Rp1));
        a = __fadd_rn(a, __fmul_rn(z, Rp2));
        vv[j] = __fadd_rn(a, Tp);
    }
    float scale = __fmul_rn(fminf(Hf, Wf), 0.5f);
    float fx = __fdiv_rn(K[0], scale);
    float fy = __fdiv_rn(K[4], scale);
    float p0x = -__fdiv_rn(__fsub_rn(K[2], __fmul_rn(Wf, 0.5f)), scale);
    float p0y = -__fdiv_rn(__fsub_rn(K[5], __fmul_rn(Hf, 0.5f)), scale);

    float zz = vv[2];
    g_vx[v] = __fadd_rn(__fdiv_rn(__fmul_rn(fx, vv[0]), zz), p0x);
    g_vy[v] = __fadd_rn(__fdiv_rn(__fmul_rn(fy, vv[1]), zz), p0y);
    g_vz[v] = zz;
}

// ------------------------- per-face precompute -----------------------------
__global__ void k_face(const int* __restrict__ faces, int Fn)
{
    int f = blockIdx.x * blockDim.x + threadIdx.x;
    if (f >= Fn) return;
    int i0 = faces[3 * f + 0], i1 = faces[3 * f + 1], i2 = faces[3 * f + 2];
    float x0 = g_vx[i0], y0 = g_vy[i0], z0 = g_vz[i0];
    float x1 = g_vx[i1], y1 = g_vy[i1], z1 = g_vz[i1];
    float x2 = g_vx[i2], y2 = g_vy[i2], z2 = g_vz[i2];

    float area = __fsub_rn(__fmul_rn(__fsub_rn(x1, x0), __fsub_rn(y2, y0)),
                           __fmul_rn(__fsub_rn(y1, y0), __fsub_rn(x2, x0)));
    bool ok = (area > 1e-8f) && (z0 > 0.0f) && (z1 > 0.0f) && (z2 > 0.0f);
    float inva = ok ? __fdiv_rn(1.0f, area) : 0.0f;

    float zmn = fminf(z0, fminf(z1, z2));
    const float M = 5e-3f;
    g_pa[f] = make_float4(x0, y0, z0, inva);
    g_pb[f] = make_float4(x1, y1, z1, __fmul_rn(z0, z1));
    g_pc[f] = make_float4(x2, y2, z2, zmn - 1e-4f);
    g_pd[f] = make_float4(fminf(x0, fminf(x1, x2)) - M,
                          fmaxf(x0, fmaxf(x1, x2)) + M,
                          fminf(y0, fminf(y1, y2)) - M,
                          fmaxf(y0, fmaxf(y1, y2)) + M);
}

// ------------------------- tile binning ------------------------------------
__global__ void k_tinit(int ntiles)
{
    int t = blockIdx.x * blockDim.x + threadIdx.x;
    if (t < ntiles) g_tcount[t] = 0;
}

__device__ __forceinline__ bool tile_range(float4 d, int W, int H,
                                           int& tx0, int& tx1, int& ty0, int& ty1)
{
    // px = 1 - (2j+1)/W is decreasing in j
    float jmin_f = ((1.0f - d.y) * (float)W - 1.0f) * 0.5f;
    float jmax_f = ((1.0f - d.x) * (float)W - 1.0f) * 0.5f;
    int j0 = max(0, (int)floorf(jmin_f) - 1);
    int j1 = min(W - 1, (int)ceilf(jmax_f) + 1);
    if (j0 > j1) return false;
    float imin_f = ((1.0f - d.w) * (float)H - 1.0f) * 0.5f;
    float imax_f = ((1.0f - d.z) * (float)H - 1.0f) * 0.5f;
    int i0 = max(0, (int)floorf(imin_f) - 1);
    int i1 = min(H - 1, (int)ceilf(imax_f) + 1);
    if (i0 > i1) return false;
    tx0 = j0 / TILE; tx1 = j1 / TILE;
    ty0 = i0 / TILE; ty1 = i1 / TILE;
    return true;
}

__global__ void k_tcount(int Fn, int W, int H, int tilesX)
{
    int f = blockIdx.x * blockDim.x + threadIdx.x;
    if (f >= Fn) return;
    if (g_pa[f].w <= 0.0f) return;                 // invalid face: can never win
    int tx0, tx1, ty0, ty1;
    if (!tile_range(g_pd[f], W, H, tx0, tx1, ty0, ty1)) return;
    for (int ty = ty0; ty <= ty1; ty++)
        for (int tx = tx0; tx <= tx1; tx++)
            atomicAdd(&g_tcount[ty * tilesX + tx], 1);
}

__global__ void k_tscan(int ntiles)   // 1 block, 1024 threads; ntiles <= 1024
{
    __shared__ int tmp[1024];
    int t = threadIdx.x;
    int v = (t < ntiles) ? g_tcount[t] : 0;
    tmp[t] = v;
    __syncthreads();
    for (int off = 1; off < 1024; off <<= 1) {
        int a = 0;
        if (t >= off) a = tmp[t - off];
        __syncthreads();
        if (t >= off) tmp[t] += a;
        __syncthreads();
    }
    if (t < ntiles) {
        int start = tmp[t] - v;
        g_tstart[t] = start;
        g_tcur[t]   = start;
    }
}

__global__ void k_tscatter(int Fn, int W, int H, int tilesX)
{
    int f = blockIdx.x * blockDim.x + threadIdx.x;
    if (f >= Fn) return;
    if (g_pa[f].w <= 0.0f) return;
    int tx0, tx1, ty0, ty1;
    if (!tile_range(g_pd[f], W, H, tx0, tx1, ty0, ty1)) return;
    for (int ty = ty0; ty <= ty1; ty++)
        for (int tx = tx0; tx <= tx1; tx++) {
            int p = atomicAdd(&g_tcur[ty * tilesX + tx], 1);
            if (p < TLCAP) g_tlist[p] = f;
        }
}

// ------------------------- exact bary (reference op order) -----------------
__device__ __forceinline__ void eval_exact(
    float px, float py,
    float x0, float y0, float z0, float x1, float y1, float z1,
    float x2, float y2, float z2, float inva, float z01,
    bool& inside, float& zpix, float& d0, float& d1, float& d2)
{
    float dx0 = __fsub_rn(x0, px), dy0 = __fsub_rn(y0, py);
    float dx1 = __fsub_rn(x1, px), dy1 = __fsub_rn(y1, py);
    float dx2 = __fsub_rn(x2, px), dy2 = __fsub_rn(y2, py);
    float w0 = __fmul_rn(__fsub_rn(__fmul_rn(dx1, dy2), __fmul_rn(dy1, dx2)), inva);
    float w1 = __fmul_rn(__fsub_rn(__fmul_rn(dx2, dy0), __fmul_rn(dy2, dx0)), inva);
    float w2 = __fmul_rn(__fsub_rn(__fmul_rn(dx0, dy1), __fmul_rn(dy0, dx1)), inva);
    inside = (w0 >= 0.0f) && (w1 >= 0.0f) && (w2 >= 0.0f);
    if (!inside) { zpix = f_inf(); d0 = d1 = d2 = 0.0f; return; }
    float l0 = __fmul_rn(__fmul_rn(w0, z1), z2);
    float l1 = __fmul_rn(__fmul_rn(z0, w1), z2);
    float l2 = __fmul_rn(z01, w2);
    float s  = __fadd_rn(__fadd_rn(l0, l1), l2);
    float sden = (s == 0.0f) ? 1.0f : s;
    float b0 = __fdiv_rn(l0, sden);
    float b1 = __fdiv_rn(l1, sden);
    float b2 = __fdiv_rn(l2, sden);
    b0 = fmaxf(b0, 0.0f); b1 = fmaxf(b1, 0.0f); b2 = fmaxf(b2, 0.0f);
    float sb = __fadd_rn(__fadd_rn(b0, b1), b2);
    float den2 = fmaxf(sb, 1e-8f);
    d0 = __fdiv_rn(b0, den2);
    d1 = __fdiv_rn(b1, den2);
    d2 = __fdiv_rn(b2, den2);
    zpix = __fadd_rn(__fadd_rn(__fmul_rn(d0, z0), __fmul_rn(d1, z1)),
                     __fmul_rn(d2, z2));
}

// ------------------------- rasterize (binned tiles) ------------------------
__global__ void __launch_bounds__(256) k_raster(int W, int H, int npix, int tilesX)
{
    __shared__ float4 sa[CHK], sb[CHK], sc[CHK], sd[CHK];
    __shared__ int    sfid[CHK];

    int tile = blockIdx.x;
    int split = blockIdx.y;
    int tx = tile % tilesX, ty = tile / tilesX;
    int lx = threadIdx.x & (TILE - 1), ly = threadIdx.x / TILE;
    int j = tx * TILE + lx, i = ty * TILE + ly;
    bool live = (j < W) && (i < H);

    float px = 0.0f, py = 0.0f;
    if (live) {
        px = __fsub_rn(1.0f, __fdiv_rn(__fadd_rn(__fmul_rn(2.0f, (float)j), 1.0f), (float)W));
        py = __fsub_rn(1.0f, __fdiv_rn(__fadd_rn(__fmul_rn(2.0f, (float)i), 1.0f), (float)H));
    }

    int start = g_tstart[tile];
    int cnt   = g_tcount[tile];
    int per = (cnt + NSPLIT - 1) / NSPLIT;
    int s0 = start + split * per;
    int s1 = min(start + cnt, s0 + per);

    float bestZ = f_inf();
    int   bestI = -1;

    for (int base = s0; base < s1; base += CHK) {
        int n = min(CHK, s1 - base);
        __syncthreads();
        if ((int)threadIdx.x < n) {
            int fid = g_tlist[base + threadIdx.x];
            sfid[threadIdx.x] = fid;
            sa[threadIdx.x] = g_pa[fid];
            sb[threadIdx.x] = g_pb[fid];
            sc[threadIdx.x] = g_pc[fid];
            sd[threadIdx.x] = g_pd[fid];
        }
        __syncthreads();
        if (!live) continue;
        for (int k = 0; k < n; k++) {
            float zskip = sc[k].w;
            if (zskip >= bestZ) continue;                 // conservative z cull
            float4 d = sd[k];
            if (px < d.x || px > d.y || py < d.z || py > d.w) continue;
            float4 a = sa[k], b = sb[k], c = sc[k];
            bool inside; float zpix, e0, e1, e2;
            eval_exact(px, py,
                       a.x, a.y, a.z, b.x, b.y, b.z, c.x, c.y, c.z,
                       a.w, b.w, inside, zpix, e0, e1, e2);
            if (inside) {
                int idx = sfid[k];
                // lexicographic (z, origIdx) == argmin-first semantics
                if (zpix < bestZ || (zpix == bestZ && idx < bestI)) {
                    bestZ = zpix; bestI = idx;
                }
            }
        }
    }
    if (live) {
        int pix = i * W + j;
        g_pz[split * npix + pix]   = bestZ;
        g_pidx[split * npix + pix] = bestI;
    }
}

// ------------------------- merge + scalar outputs --------------------------
__global__ void k_merge(float* __restrict__ out, int W, int H, int npix, int C)
{
    int pix = blockIdx.x * blockDim.x + threadIdx.x;
    if (pix >= npix) return;
    float bz = f_inf(); int bi = -1;
#pragma unroll
    for (int sp = 0; sp < NSPLIT; sp++) {
        float z = g_pz[sp * npix + pix];
        int  id = g_pidx[sp * npix + pix];
        if (id >= 0 && (z < bz || (z == bz && id < bi))) { bz = z; bi = id; }
    }

    float p2f, zb, ba0, ba1, ba2, ds;
    if (bi < 0) {
        p2f = -1.0f; zb = -1.0f; ba0 = ba1 = ba2 = -1.0f; ds = -1.0f;
    } else {
        int i = pix / W, j = pix % W;
        float px = __fsub_rn(1.0f, __fdiv_rn(__fadd_rn(__fmul_rn(2.0f, (float)j), 1.0f), (float)W));
        float py = __fsub_rn(1.0f, __fdiv_rn(__fadd_rn(__fmul_rn(2.0f, (float)i), 1.0f), (float)H));
        float4 a = g_pa[bi], b = g_pb[bi], c = g_pc[bi];
        bool inside; float zpix, e0, e1, e2;
        eval_exact(px, py, a.x, a.y, a.z, b.x, b.y, b.z, c.x, c.y, c.z,
                   a.w, b.w, inside, zpix, e0, e1, e2);
        p2f = (float)bi; zb = bz; ba0 = e0; ba1 = e1; ba2 = e2; ds = 0.0f;
        g_wb[3 * pix + 0] = e0; g_wb[3 * pix + 1] = e1; g_wb[3 * pix + 2] = e2;
    }
    g_widx[pix] = bi;

    size_t o1 = (size_t)npix * (size_t)C;
    out[o1 + pix] = p2f;
    out[o1 + npix + pix] = zb;
    out[o1 + 2 * (size_t)npix + 3 * (size_t)pix + 0] = ba0;
    out[o1 + 2 * (size_t)npix + 3 * (size_t)pix + 1] = ba1;
    out[o1 + 2 * (size_t)npix + 3 * (size_t)pix + 2] = ba2;
    out[o1 + 5 * (size_t)npix + pix] = ds;
}

// ------------------------- feature interpolation ---------------------------
__global__ void k_feats(float* __restrict__ out,
                        const float* __restrict__ feats,
                        const int* __restrict__ faces,
                        int npix, int C)
{
    int gw = (blockIdx.x * blockDim.x + threadIdx.x) >> 5;
    int lane = threadIdx.x & 31;
    if (gw >= npix) return;
    float* o = out + (size_t)gw * (size_t)C;
    int bi = g_widx[gw];
    if (bi < 0) {
        for (int c = lane; c < C; c += 32) o[c] = 0.0f;
        return;
    }
    int v0 = faces[3 * bi + 0], v1 = faces[3 * bi + 1], v2 = faces[3 * bi + 2];
    float b0 = g_wb[3 * gw + 0], b1 = g_wb[3 * gw + 1], b2 = g_wb[3 * gw + 2];
    const float* f0 = feats + (size_t)v0 * (size_t)C;
    const float* f1 = feats + (size_t)v1 * (size_t)C;
    const float* f2 = feats + (size_t)v2 * (size_t)C;
    for (int c = lane; c < C; c += 32) {
        float val = __fadd_rn(__fadd_rn(__fmul_rn(b0, f0[c]),
                                        __fmul_rn(b1, f1[c])),
                              __fmul_rn(b2, f2[c]));
        o[c] = val;
    }
}

// ------------------------- launch -----------------------------------------
extern "C" void kernel_launch(void* const* d_in, const int* in_sizes, int n_in,
                              void* d_out, int out_size)
{
    const float* positions = (const float*)d_in[0];
    const float* features  = (const float*)d_in[1];
    const int*   faces     = (const int*)d_in[2];
    const float* K         = (const float*)d_in[3];
    const float* RT        = (const float*)d_in[4];

    int V  = in_sizes[0] / 3;
    int C  = in_sizes[1] / V;
    int Fn = in_sizes[2] / 3;
    int npix = out_size / (C + 6);
    int W = (int)(sqrt((double)npix) + 0.5);
    if (W <= 0) W = 1;
    int H = npix / W;
    float* out = (float*)d_out;

    int tilesX = (W + TILE - 1) / TILE;
    int tilesY = (H + TILE - 1) / TILE;
    int ntiles = tilesX * tilesY;

    k_vertex<<<(V + 255) / 256, 256>>>(positions, K, RT, V, (float)W, (float)H);
    k_face<<<(Fn + 255) / 256, 256>>>(faces, Fn);
    k_tinit<<<(ntiles + 255) / 256, 256>>>(ntiles);
    k_tcount<<<(Fn + 255) / 256, 256>>>(Fn, W, H, tilesX);
    k_tscan<<<1, 1024>>>(ntiles);
    k_tscatter<<<(Fn + 255) / 256, 256>>>(Fn, W, H, tilesX);

    dim3 rg(ntiles, NSPLIT);
    k_raster<<<rg, 256>>>(W, H, npix, tilesX);

    k_merge<<<(npix + 255) / 256, 256>>>(out, W, H, npix, C);
    k_feats<<<(npix + 7) / 8, 256>>>(out, features, faces, npix, C);
}

// round 4
// speedup vs baseline: 5.9393x; 2.0636x over previous
#include <cuda_runtime.h>
#include <math.h>

// ---------------------------------------------------------------------------
// Mesh rasterizer — z-sorted face stream + fused tile filter in raster.
// Output (float32): [pix_feats npix*C][p2f npix][zbuf npix][bary 3npix][dists npix]
// ---------------------------------------------------------------------------

#define VMAX    16384
#define FMAX    32768
#define PIXMAX  65536
#define TILE    16
#define NBUCK   1024
#define CHK     256
#define NCHMAX  (FMAX / CHK)
#define NSPLIT  4

__device__ float g_vx[VMAX], g_vy[VMAX], g_vz[VMAX];

// unsorted per-face packed records (indexed by original face id; merge/feats)
// pa=(x0,y0,z0,inva) pb=(x1,y1,z1,z0*z1) pc=(x2,y2,z2,zskip) pd=(bxmin,bxmax,bymin,bymax)
__device__ float4 g_pa[FMAX], g_pb[FMAX], g_pc[FMAX], g_pd[FMAX];

// z-sorted compacted valid faces
__device__ float4 o_pa[FMAX], o_pb[FMAX], o_pc[FMAX], o_pd[FMAX];
__device__ int    o_fid[FMAX];

__device__ unsigned g_zmin_u, g_zmax_u;
__device__ int      g_hist[NBUCK];
__device__ int      g_boff[NBUCK];
__device__ int      g_nvalid;
__device__ unsigned g_chmin_u[NCHMAX];
__device__ float    g_chsuf[NCHMAX];

__device__ float g_pz[NSPLIT * PIXMAX];
__device__ int   g_pidx[NSPLIT * PIXMAX];
__device__ float g_wb[PIXMAX * 3];
__device__ int   g_widx[PIXMAX];

__device__ __forceinline__ float f_inf() { return __int_as_float(0x7f800000); }

__device__ __forceinline__ unsigned f2o(float f) {
    unsigned u = __float_as_uint(f);
    return (u & 0x80000000u) ? ~u : (u | 0x80000000u);
}
__device__ __forceinline__ float o2f(unsigned u) {
    unsigned v = (u & 0x80000000u) ? (u & 0x7fffffffu) : ~u;
    return __uint_as_float(v);
}

// ------------------------- init -------------------------------------------
__global__ void k_init()
{
    int t = threadIdx.x;
    if (t < NBUCK)  g_hist[t] = 0;
    if (t < NCHMAX) g_chmin_u[t] = 0xFFFFFFFFu;
    if (t == 0) { g_zmin_u = 0xFFFFFFFFu; g_zmax_u = 0u; g_nvalid = 0; }
}

// ------------------------- vertex transform -------------------------------
__global__ void k_vertex(const float* __restrict__ pos,
                         const float* __restrict__ K,
                         const float* __restrict__ RT,
                         int V, float Wf, float Hf)
{
    int v = blockIdx.x * blockDim.x + threadIdx.x;
    if (v >= V) return;
    float x = pos[3 * v + 0], y = pos[3 * v + 1], z = pos[3 * v + 2];

    float vv[3];
#pragma unroll
    for (int j = 0; j < 3; j++) {
        float sg = (j == 2) ? 1.0f : -1.0f;
        float Rp0 = __fmul_rn(RT[j * 4 + 0], sg);
        float Rp1 = __fmul_rn(RT[j * 4 + 1], sg);
        float Rp2 = __fmul_rn(RT[j * 4 + 2], sg);
        float Tp  = __fmul_rn(RT[j * 4 + 3], sg);
        float a = __fmul_rn(x, Rp0);
        a = __fadd_rn(a, __fmul_rn(y, Rp1));
        a = __fadd_rn(a, __fmul_rn(z, Rp2));
        vv[j] = __fadd_rn(a, Tp);
    }
    float scale = __fmul_rn(fminf(Hf, Wf), 0.5f);
    float fx = __fdiv_rn(K[0], scale);
    float fy = __fdiv_rn(K[4], scale);
    float p0x = -__fdiv_rn(__fsub_rn(K[2], __fmul_rn(Wf, 0.5f)), scale);
    float p0y = -__fdiv_rn(__fsub_rn(K[5], __fmul_rn(Hf, 0.5f)), scale);

    float zz = vv[2];
    g_vx[v] = __fadd_rn(__fdiv_rn(__fmul_rn(fx, vv[0]), zz), p0x);
    g_vy[v] = __fadd_rn(__fdiv_rn(__fmul_rn(fy, vv[1]), zz), p0y);
    g_vz[v] = zz;
}

// ------------------------- per-face precompute -----------------------------
__global__ void k_face(const int* __restrict__ faces, int Fn)
{
    int f = blockIdx.x * blockDim.x + threadIdx.x;
    bool in_range = (f < Fn);
    bool ok = false;
    float zskip = 0.0f;
    if (in_range) {
        int i0 = faces[3 * f + 0], i1 = faces[3 * f + 1], i2 = faces[3 * f + 2];
        float x0 = g_vx[i0], y0 = g_vy[i0], z0 = g_vz[i0];
        float x1 = g_vx[i1], y1 = g_vy[i1], z1 = g_vz[i1];
        float x2 = g_vx[i2], y2 = g_vy[i2], z2 = g_vz[i2];

        float area = __fsub_rn(__fmul_rn(__fsub_rn(x1, x0), __fsub_rn(y2, y0)),
                               __fmul_rn(__fsub_rn(y1, y0), __fsub_rn(x2, x0)));
        ok = (area > 1e-8f) && (z0 > 0.0f) && (z1 > 0.0f) && (z2 > 0.0f);
        float inva = ok ? __fdiv_rn(1.0f, area) : 0.0f;

        float zmn = fminf(z0, fminf(z1, z2));
        zskip = zmn - 1e-4f;
        const float M = 5e-3f;
        g_pa[f] = make_float4(x0, y0, z0, inva);
        g_pb[f] = make_float4(x1, y1, z1, __fmul_rn(z0, z1));
        g_pc[f] = make_float4(x2, y2, z2, zskip);
        g_pd[f] = make_float4(fminf(x0, fminf(x1, x2)) - M,
                              fmaxf(x0, fmaxf(x1, x2)) + M,
                              fminf(y0, fminf(y1, y2)) - M,
                              fmaxf(y0, fmaxf(y1, y2)) + M);
    }
    // warp-reduced range atomics
    unsigned zmin_c = (in_range && ok) ? f2o(zskip) : 0xFFFFFFFFu;
    unsigned zmax_c = (in_range && ok) ? f2o(zskip) : 0u;
#pragma unroll
    for (int off = 16; off > 0; off >>= 1) {
        zmin_c = min(zmin_c, __shfl_down_sync(0xffffffffu, zmin_c, off));
        zmax_c = max(zmax_c, __shfl_down_sync(0xffffffffu, zmax_c, off));
    }
    if ((threadIdx.x & 31) == 0) {
        if (zmin_c != 0xFFFFFFFFu) atomicMin(&g_zmin_u, zmin_c);
        if (zmax_c != 0u)          atomicMax(&g_zmax_u, zmax_c);
    }
}

// ------------------------- z bucket sort -----------------------------------
__device__ __forceinline__ int bucket_of(float z)
{
    float zmin = o2f(g_zmin_u), zmax = o2f(g_zmax_u);
    float r = zmax - zmin;
    int b = 0;
    if (r > 0.0f) b = (int)(((z - zmin) / r) * (float)NBUCK);
    if (b < 0) b = 0;
    if (b > NBUCK - 1) b = NBUCK - 1;
    return b;
}

__global__ void k_hist(int Fn)
{
    int f = blockIdx.x * blockDim.x + threadIdx.x;
    if (f >= Fn) return;
    if (g_pa[f].w > 0.0f) atomicAdd(&g_hist[bucket_of(g_pc[f].w)], 1);
}

__global__ void k_scan()   // 1 block, NBUCK threads
{
    __shared__ int tmp[NBUCK];
    int t = threadIdx.x;
    int v = g_hist[t];
    tmp[t] = v;
    __syncthreads();
    for (int off = 1; off < NBUCK; off <<= 1) {
        int a = 0;
        if (t >= off) a = tmp[t - off];
        __syncthreads();
        if (t >= off) tmp[t] += a;
        __syncthreads();
    }
    g_boff[t] = tmp[t] - v;
    if (t == NBUCK - 1) g_nvalid = tmp[t];
}

__global__ void k_scatter(int Fn)
{
    int f = blockIdx.x * blockDim.x + threadIdx.x;
    if (f >= Fn) return;
    if (g_pa[f].w <= 0.0f) return;
    float zs = g_pc[f].w;
    int b = bucket_of(zs);
    int p = atomicAdd(&g_boff[b], 1);
    o_pa[p] = g_pa[f]; o_pb[p] = g_pb[f]; o_pc[p] = g_pc[f]; o_pd[p] = g_pd[f];
    o_fid[p] = f;
    atomicMin(&g_chmin_u[p / CHK], f2o(zs));
}

__global__ void k_suffix()   // 1 thread
{
    int n = g_nvalid;
    int nch = (n + CHK - 1) / CHK;
    float suf = f_inf();
    for (int c = nch - 1; c >= 0; c--) {
        suf = fminf(suf, o2f(g_chmin_u[c]));
        g_chsuf[c] = suf;
    }
}

// ------------------------- exact bary (reference op order) -----------------
__device__ __forceinline__ void eval_exact(
    float px, float py,
    float x0, float y0, float z0, float x1, float y1, float z1,
    float x2, float y2, float z2, float inva, float z01,
    bool& inside, float& zpix, float& d0, float& d1, float& d2)
{
    float dx0 = __fsub_rn(x0, px), dy0 = __fsub_rn(y0, py);
    float dx1 = __fsub_rn(x1, px), dy1 = __fsub_rn(y1, py);
    float dx2 = __fsub_rn(x2, px), dy2 = __fsub_rn(y2, py);
    float w0 = __fmul_rn(__fsub_rn(__fmul_rn(dx1, dy2), __fmul_rn(dy1, dx2)), inva);
    float w1 = __fmul_rn(__fsub_rn(__fmul_rn(dx2, dy0), __fmul_rn(dy2, dx0)), inva);
    float w2 = __fmul_rn(__fsub_rn(__fmul_rn(dx0, dy1), __fmul_rn(dy0, dx1)), inva);
    inside = (w0 >= 0.0f) && (w1 >= 0.0f) && (w2 >= 0.0f);
    if (!inside) { zpix = f_inf(); d0 = d1 = d2 = 0.0f; return; }
    float l0 = __fmul_rn(__fmul_rn(w0, z1), z2);
    float l1 = __fmul_rn(__fmul_rn(z0, w1), z2);
    float l2 = __fmul_rn(z01, w2);
    float s  = __fadd_rn(__fadd_rn(l0, l1), l2);
    float sden = (s == 0.0f) ? 1.0f : s;
    float b0 = __fdiv_rn(l0, sden);
    float b1 = __fdiv_rn(l1, sden);
    float b2 = __fdiv_rn(l2, sden);
    b0 = fmaxf(b0, 0.0f); b1 = fmaxf(b1, 0.0f); b2 = fmaxf(b2, 0.0f);
    float sb = __fadd_rn(__fadd_rn(b0, b1), b2);
    float den2 = fmaxf(sb, 1e-8f);
    d0 = __fdiv_rn(b0, den2);
    d1 = __fdiv_rn(b1, den2);
    d2 = __fdiv_rn(b2, den2);
    zpix = __fadd_rn(__fadd_rn(__fmul_rn(d0, z0), __fmul_rn(d1, z1)),
                     __fmul_rn(d2, z2));
}

// ------------------------- fused raster ------------------------------------
__global__ void __launch_bounds__(256) k_raster(int W, int H, int npix, int tilesX)
{
    __shared__ float4 sa[CHK], sb[CHK], sc[CHK], sd[CHK];
    __shared__ int    sfid[CHK];
    __shared__ int    scnt;

    int tile = blockIdx.x;
    int split = blockIdx.y;
    int tx = tile % tilesX, ty = tile / tilesX;
    int lx = threadIdx.x & (TILE - 1), ly = threadIdx.x / TILE;
    int j = tx * TILE + lx, i = ty * TILE + ly;
    bool live = (j < W) && (i < H);

    float px = 0.0f, py = 0.0f;
    if (live) {
        px = __fsub_rn(1.0f, __fdiv_rn(__fadd_rn(__fmul_rn(2.0f, (float)j), 1.0f), (float)W));
        py = __fsub_rn(1.0f, __fdiv_rn(__fadd_rn(__fmul_rn(2.0f, (float)i), 1.0f), (float)H));
    }
    // tile ndc rect (px decreasing in j, py decreasing in i); exact pixel formulas
    int jlo = tx * TILE, jhi = min(W - 1, tx * TILE + TILE - 1);
    int ilo = ty * TILE, ihi = min(H - 1, ty * TILE + TILE - 1);
    float pxHi = __fsub_rn(1.0f, __fdiv_rn(__fadd_rn(__fmul_rn(2.0f, (float)jlo), 1.0f), (float)W));
    float pxLo = __fsub_rn(1.0f, __fdiv_rn(__fadd_rn(__fmul_rn(2.0f, (float)jhi), 1.0f), (float)W));
    float pyHi = __fsub_rn(1.0f, __fdiv_rn(__fadd_rn(__fmul_rn(2.0f, (float)ilo), 1.0f), (float)H));
    float pyLo = __fsub_rn(1.0f, __fdiv_rn(__fadd_rn(__fmul_rn(2.0f, (float)ihi), 1.0f), (float)H));

    int n = g_nvalid;
    int nch = (n + CHK - 1) / CHK;
    float bestZ = f_inf();
    int   bestI = -1;
    int lane = threadIdx.x & 31;

    for (int c = split; c < nch; c += NSPLIT) {
        // all faces in chunks >= c have zskip >= g_chsuf[c]
        int done = (!live) || (g_chsuf[c] >= bestZ);
        if (__syncthreads_and(done)) break;

        if (threadIdx.x == 0) scnt = 0;
        __syncthreads();

        int base = c * CHK;
        int cnt = min(CHK, n - base);
        int t = threadIdx.x;
        bool keep = false;
        float4 d;
        int g = base + t;
        if (t < cnt) {
            d = o_pd[g];
            keep = (d.x <= pxHi) && (d.y >= pxLo) && (d.z <= pyHi) && (d.w >= pyLo);
        }
        unsigned m = __ballot_sync(0xffffffffu, keep);
        int nw = __popc(m);
        int basew = 0;
        if (lane == 0 && nw) basew = atomicAdd(&scnt, nw);
        basew = __shfl_sync(0xffffffffu, basew, 0);
        if (keep) {
            int pos = basew + __popc(m & ((1u << lane) - 1u));
            sa[pos] = o_pa[g]; sb[pos] = o_pb[g]; sc[pos] = o_pc[g];
            sd[pos] = d; sfid[pos] = o_fid[g];
        }
        __syncthreads();
        int ns = scnt;
        if (live) {
            for (int k = 0; k < ns; k++) {
                if (sc[k].w >= bestZ) continue;               // conservative z cull
                float4 dd = sd[k];
                if (px < dd.x || px > dd.y || py < dd.z || py > dd.w) continue;
                float4 a = sa[k], b = sb[k], cc = sc[k];
                bool inside; float zpix, e0, e1, e2;
                eval_exact(px, py, a.x, a.y, a.z, b.x, b.y, b.z,
                           cc.x, cc.y, cc.z, a.w, b.w,
                           inside, zpix, e0, e1, e2);
                if (inside) {
                    int idx = sfid[k];
                    if (zpix < bestZ || (zpix == bestZ && idx < bestI)) {
                        bestZ = zpix; bestI = idx;
                    }
                }
            }
        }
    }
    if (live) {
        int pix = i * W + j;
        g_pz[split * npix + pix]   = bestZ;
        g_pidx[split * npix + pix] = bestI;
    }
}

// ------------------------- merge + scalar outputs --------------------------
__global__ void k_merge(float* __restrict__ out, int W, int H, int npix, int C)
{
    int pix = blockIdx.x * blockDim.x + threadIdx.x;
    if (pix >= npix) return;
    float bz = f_inf(); int bi = -1;
#pragma unroll
    for (int sp = 0; sp < NSPLIT; sp++) {
        float z = g_pz[sp * npix + pix];
        int  id = g_pidx[sp * npix + pix];
        if (id >= 0 && (z < bz || (z == bz && id < bi))) { bz = z; bi = id; }
    }

    float p2f, zb, ba0, ba1, ba2, ds;
    if (bi < 0) {
        p2f = -1.0f; zb = -1.0f; ba0 = ba1 = ba2 = -1.0f; ds = -1.0f;
    } else {
        int i = pix / W, j = pix % W;
        float px = __fsub_rn(1.0f, __fdiv_rn(__fadd_rn(__fmul_rn(2.0f, (float)j), 1.0f), (float)W));
        float py = __fsub_rn(1.0f, __fdiv_rn(__fadd_rn(__fmul_rn(2.0f, (float)i), 1.0f), (float)H));
        float4 a = g_pa[bi], b = g_pb[bi], c = g_pc[bi];
        bool inside; float zpix, e0, e1, e2;
        eval_exact(px, py, a.x, a.y, a.z, b.x, b.y, b.z, c.x, c.y, c.z,
                   a.w, b.w, inside, zpix, e0, e1, e2);
        p2f = (float)bi; zb = bz; ba0 = e0; ba1 = e1; ba2 = e2; ds = 0.0f;
        g_wb[3 * pix + 0] = e0; g_wb[3 * pix + 1] = e1; g_wb[3 * pix + 2] = e2;
    }
    g_widx[pix] = bi;

    size_t o1 = (size_t)npix * (size_t)C;
    out[o1 + pix] = p2f;
    out[o1 + npix + pix] = zb;
    out[o1 + 2 * (size_t)npix + 3 * (size_t)pix + 0] = ba0;
    out[o1 + 2 * (size_t)npix + 3 * (size_t)pix + 1] = ba1;
    out[o1 + 2 * (size_t)npix + 3 * (size_t)pix + 2] = ba2;
    out[o1 + 5 * (size_t)npix + pix] = ds;
}

// ------------------------- feature interpolation ---------------------------
__global__ void k_feats(float* __restrict__ out,
                        const float* __restrict__ feats,
                        const int* __restrict__ faces,
                        int npix, int C)
{
    int gw = (blockIdx.x * blockDim.x + threadIdx.x) >> 5;
    int lane = threadIdx.x & 31;
    if (gw >= npix) return;
    float* o = out + (size_t)gw * (size_t)C;
    int bi = g_widx[gw];
    if (bi < 0) {
        for (int c = lane; c < C; c += 32) o[c] = 0.0f;
        return;
    }
    int v0 = faces[3 * bi + 0], v1 = faces[3 * bi + 1], v2 = faces[3 * bi + 2];
    float b0 = g_wb[3 * gw + 0], b1 = g_wb[3 * gw + 1], b2 = g_wb[3 * gw + 2];
    const float* f0 = feats + (size_t)v0 * (size_t)C;
    const float* f1 = feats + (size_t)v1 * (size_t)C;
    const float* f2 = feats + (size_t)v2 * (size_t)C;
    for (int c = lane; c < C; c += 32) {
        float val = __fadd_rn(__fadd_rn(__fmul_rn(b0, f0[c]),
                                        __fmul_rn(b1, f1[c])),
                              __fmul_rn(b2, f2[c]));
        o[c] = val;
    }
}

// ------------------------- launch -----------------------------------------
extern "C" void kernel_launch(void* const* d_in, const int* in_sizes, int n_in,
                              void* d_out, int out_size)
{
    const float* positions = (const float*)d_in[0];
    const float* features  = (const float*)d_in[1];
    const int*   faces     = (const int*)d_in[2];
    const float* K         = (const float*)d_in[3];
    const float* RT        = (const float*)d_in[4];

    int V  = in_sizes[0] / 3;
    int C  = in_sizes[1] / V;
    int Fn = in_sizes[2] / 3;
    int npix = out_size / (C + 6);
    int W = (int)(sqrt((double)npix) + 0.5);
    if (W <= 0) W = 1;
    int H = npix / W;
    float* out = (float*)d_out;

    int tilesX = (W + TILE - 1) / TILE;
    int tilesY = (H + TILE - 1) / TILE;
    int ntiles = tilesX * tilesY;

    k_init<<<1, 1024>>>();
    k_vertex<<<(V + 255) / 256, 256>>>(positions, K, RT, V, (float)W, (float)H);
    k_face<<<(Fn + 255) / 256, 256>>>(faces, Fn);
    k_hist<<<(Fn + 255) / 256, 256>>>(Fn);
    k_scan<<<1, NBUCK>>>();
    k_scatter<<<(Fn + 255) / 256, 256>>>(Fn);
    k_suffix<<<1, 1>>>();

    dim3 rg(ntiles, NSPLIT);
    k_raster<<<rg, 256>>>(W, H, npix, tilesX);

    k_merge<<<(npix + 255) / 256, 256>>>(out, W, H, npix, C);
    k_feats<<<(npix + 7) / 8, 256>>>(out, features, faces, npix, C);
}